// round 4
// baseline (speedup 1.0000x reference)
#include <cuda_runtime.h>
#include <cstdint>

// Problem shape (fixed by reference): B=32, S=128, V=32000
// loss = -sum_{b,s} prob[b,s,target[b,s]] * reward[b]
//
// Latency-bound: 4096 scattered gathers -> 1 scalar. R3 post-mortem: the
// store+__threadfence(gpu->CCTL.IVALL L1-flush)+ticket+reload tail cost ~2.5us.
// This version: single float accumulator, ordering via PTX acq_rel atomics
// (no MEMBAR/IVALL), last-arriver finalizes single-threaded. 16 CTAs x 256.

#define B_ 32
#define S_ 128
#define V_ 32000
#define N_ (B_ * S_)      // 4096
#define NCTA_ 16
#define NTHR_ 256

__device__ float        g_sum    = 0.0f;  // self-resets each launch
__device__ unsigned int g_ticket = 0;     // self-resets each launch

__global__ void rl_loss_kernel(const float* __restrict__ prob,
                               const int* __restrict__ target,
                               const float* __restrict__ reward,
                               float* __restrict__ out) {
    __shared__ float s_warp[NTHR_ / 32];

    int i = blockIdx.x * NTHR_ + threadIdx.x;        // 0..4095
    int t = __ldg(&target[i]);                       // coalesced int32 load
    float v = __ldg(&prob[(long long)i * V_ + t]);   // scattered gather
    float r = __ldg(&reward[i >> 7]);                // S_ = 128
    float x = v * r;

    // warp tree-reduce
    #pragma unroll
    for (int off = 16; off > 0; off >>= 1)
        x += __shfl_xor_sync(0xFFFFFFFFu, x, off);

    int warp = threadIdx.x >> 5;
    if ((threadIdx.x & 31) == 0) s_warp[warp] = x;
    __syncthreads();

    if (threadIdx.x == 0) {
        float p = 0.0f;
        #pragma unroll
        for (int w = 0; w < NTHR_ / 32; w++) p += s_warp[w];

        // Accumulate into the single global sum (relaxed; L2-serialized).
        atomicAdd(&g_sum, p);

        // Ticket with acq_rel: release orders our g_sum add before the
        // increment; acquire makes every earlier CTA's g_sum add visible
        // to the last arriver. No MEMBAR / L1 flush emitted.
        unsigned int old;
        asm volatile("atom.acq_rel.gpu.add.u32 %0, [%1], 1;"
                     : "=r"(old) : "l"(&g_ticket) : "memory");

        if (old == NCTA_ - 1) {
            // All 16 partials are in g_sum. Read it, finalize, reset.
            float tot = atomicAdd(&g_sum, 0.0f);
            *out = -tot;                       // overwrites harness poison
            atomicExch(&g_sum, 0.0f);          // reset for next graph replay
            atomicExch(&g_ticket, 0u);
        }
    }
}

extern "C" void kernel_launch(void* const* d_in, const int* in_sizes, int n_in,
                              void* d_out, int out_size) {
    // Identify inputs by element count, robust to ordering:
    //   prob: B*S*V = 131,072,000   target: B*S = 4096   reward: B = 32
    const float* prob   = nullptr;
    const int*   target = nullptr;
    const float* reward = nullptr;
    for (int k = 0; k < n_in; k++) {
        if (in_sizes[k] == N_ * V_)      prob   = (const float*)d_in[k];
        else if (in_sizes[k] == N_)      target = (const int*)d_in[k];
        else if (in_sizes[k] == B_)      reward = (const float*)d_in[k];
    }
    float* out = (float*)d_out;

    // Single graph node: 16 CTAs x 256 threads, one gather each.
    rl_loss_kernel<<<NCTA_, NTHR_>>>(prob, target, reward, out);
}

// round 5
// speedup vs baseline: 1.1065x; 1.1065x over previous
#include <cuda_runtime.h>
#include <cstdint>

// Problem shape (fixed by reference): B=32, S=128, V=32000
// loss = -sum_{b,s} prob[b,s,target[b,s]] * reward[b]
//
// Latency-bound: 4096 scattered gathers -> 1 scalar; real work ~0.5us, the
// rest is fixed launch ramp. R2..R4 post-mortem: tail micro-structure moves
// ~0.5us; memset node cost 2.5us. This version = fastest observed kernel
// shape (32x128, per-warp atomics, no smem/syncthreads) + single graph node:
//   - per-warp relaxed RED into g_sum (no return)
//   - per-warp acq_rel wrapping ticket ((old&127)==127 -> last; no reset op)
//   - last warp: atomicExch(g_sum,0) reads total AND resets in one L2 op
//   - plain STG of -total overwrites the harness poison (no memset node)

#define B_ 32
#define S_ 128
#define V_ 32000
#define N_ (B_ * S_)      // 4096
#define NCTA_ 32
#define NTHR_ 128
#define NWARPS_TOTAL_ (NCTA_ * NTHR_ / 32)   // 128

__device__ float        g_sum    = 0.0f;  // read+reset by last warp each launch
__device__ unsigned int g_ticket = 0;     // wraps; 2^32 % 128 == 0

__global__ void rl_loss_kernel(const float* __restrict__ prob,
                               const int* __restrict__ target,
                               const float* __restrict__ reward,
                               float* __restrict__ out) {
    int i = blockIdx.x * NTHR_ + threadIdx.x;        // 0..4095
    float r = __ldg(&reward[i >> 7]);                // independent, issues first
    int t = __ldg(&target[i]);                       // coalesced int32
    float v = __ldg(&prob[(long long)i * V_ + t]);   // scattered gather (L2-warm)
    float x = v * r;

    // warp tree-reduce (5 shuffles)
    #pragma unroll
    for (int off = 16; off > 0; off >>= 1)
        x += __shfl_xor_sync(0xFFFFFFFFu, x, off);

    if ((threadIdx.x & 31) == 0) {
        // Relaxed accumulate (no return value -> REDG).
        asm volatile("red.relaxed.gpu.global.add.f32 [%0], %1;"
                     :: "l"(&g_sum), "f"(x) : "memory");

        // acq_rel ticket: release orders our RED before the increment;
        // acquire makes all earlier warps' REDs visible to the last arriver.
        unsigned int old;
        asm volatile("atom.acq_rel.gpu.global.add.u32 %0, [%1], 1;"
                     : "=r"(old) : "l"(&g_ticket) : "memory");

        if ((old & (NWARPS_TOTAL_ - 1)) == NWARPS_TOTAL_ - 1) {
            // Read the completed sum AND reset it for the next replay, one op.
            float tot = atomicExch(&g_sum, 0.0f);
            *out = -tot;                     // overwrites harness poison
        }
    }
}

extern "C" void kernel_launch(void* const* d_in, const int* in_sizes, int n_in,
                              void* d_out, int out_size) {
    // Identify inputs by element count, robust to ordering:
    //   prob: B*S*V = 131,072,000   target: B*S = 4096   reward: B = 32
    const float* prob   = nullptr;
    const int*   target = nullptr;
    const float* reward = nullptr;
    for (int k = 0; k < n_in; k++) {
        if (in_sizes[k] == N_ * V_)      prob   = (const float*)d_in[k];
        else if (in_sizes[k] == N_)      target = (const int*)d_in[k];
        else if (in_sizes[k] == B_)      reward = (const float*)d_in[k];
    }
    float* out = (float*)d_out;

    // Single graph node: 32 CTAs x 128 threads, one gather each.
    rl_loss_kernel<<<NCTA_, NTHR_>>>(prob, target, reward, out);
}